// round 1
// baseline (speedup 1.0000x reference)
#include <cuda_runtime.h>

// Problem constants
#define D      256
#define K      1024
#define HW     1024            // 32*32 spatial per batch
#define NTOK   32768           // 32 * 1024
#define NBLK   256             // main grid (NTOK / 128)
#define ZQN    8388608         // 32*256*32*32
#define IDX_OFF 8388608
#define LOSS_OFF 8421376

// B-tile smem geometry
#define BK    16
#define BSTR  132              // padded stride (words) to kill store conflicts
#define BBUF  (BK * BSTR)

#define SMEM_BYTES ((D * 128 + 2 * BBUF) * 4 + 128 * 4)   // A panel + B dbuf + rowIdx

__device__ float g_cnorm[K];
__device__ float g_partial[NBLK];

// ---------------------------------------------------------------------------
// Kernel 1: codebook squared norms
// ---------------------------------------------------------------------------
__global__ void cnorm_kernel(const float* __restrict__ cb) {
    int k    = blockIdx.x * 8 + (threadIdx.x >> 5);
    int lane = threadIdx.x & 31;
    const float* row = cb + k * D;
    float s = 0.f;
#pragma unroll
    for (int d = lane; d < D; d += 32) { float v = row[d]; s = fmaf(v, v, s); }
#pragma unroll
    for (int off = 16; off; off >>= 1) s += __shfl_xor_sync(0xffffffffu, s, off);
    if (lane == 0) g_cnorm[k] = s;
}

// ---------------------------------------------------------------------------
// Kernel 2: fused GEMM + argmin + gather + loss partials
// Block = 128 tokens x all 1024 codes. 256 threads, 8x8 micro-tiles.
// ---------------------------------------------------------------------------
__global__ __launch_bounds__(256, 1) void vq_main(const float* __restrict__ z,
                                                  const float* __restrict__ cb,
                                                  float* __restrict__ out) {
    extern __shared__ float sm[];
    float* As     = sm;                        // [256][128]  token panel (d-major)
    float* Bs     = sm + D * 128;              // [2][BK][BSTR]
    int*   rowIdx = (int*)(Bs + 2 * BBUF);     // [128]

    const int t   = threadIdx.x;
    const int tx  = t & 15;
    const int ty  = t >> 4;
    const int n0  = blockIdx.x * 128;
    const int b   = n0 >> 10;                  // batch index (128 | 1024 so no straddle)
    const int hw0 = n0 & 1023;
    const float* zb = z + b * (D * HW) + hw0;

    // ---- Load A panel: 128 tokens x 256 dims, stored As[d][token] ----
    {
        const int i4    = (t & 31) * 4;
        const int dbase = t >> 5;
#pragma unroll
        for (int j = 0; j < 32; j++) {
            int d = dbase + j * 8;
            float4 v = *(const float4*)(zb + d * HW + i4);
            *(float4*)(As + d * 128 + i4) = v;
        }
    }

    float best[2][4];
    int   bidx[2][4];
#pragma unroll
    for (int h = 0; h < 2; h++)
#pragma unroll
        for (int i = 0; i < 4; i++) { best[h][i] = 3.4e38f; bidx[h][i] = 0; }

    __syncthreads();

    // ---- Loop over 8 code tiles of 128 ----
    for (int tile = 0; tile < 8; tile++) {
        const int k0 = tile * 128;
        float acc[2][4][2][4];
#pragma unroll
        for (int h = 0; h < 2; h++)
#pragma unroll
            for (int i = 0; i < 4; i++)
#pragma unroll
                for (int g = 0; g < 2; g++)
#pragma unroll
                    for (int j = 0; j < 4; j++) acc[h][i][g][j] = 0.f;

        float rb[8];
        // prologue: chunk 0 -> Bs[0]
#pragma unroll
        for (int j = 0; j < 8; j++) {
            int l = j * 256 + t; int d = l & 15; int k = l >> 4;
            rb[j] = cb[(k0 + k) * D + d];
        }
#pragma unroll
        for (int j = 0; j < 8; j++) {
            int l = j * 256 + t; int d = l & 15; int k = l >> 4;
            Bs[d * BSTR + k] = rb[j];
        }
        __syncthreads();

        for (int ch = 0; ch < 16; ch++) {
            const int cur = ch & 1;
            if (ch < 15) {   // prefetch next chunk into registers
                const int dbase = (ch + 1) * BK;
#pragma unroll
                for (int j = 0; j < 8; j++) {
                    int l = j * 256 + t; int d = l & 15; int k = l >> 4;
                    rb[j] = cb[(k0 + k) * D + dbase + d];
                }
            }
            const float* Bc = Bs + cur * BBUF;
            const float* Ac = As + ch * BK * 128;
#pragma unroll
            for (int dd = 0; dd < BK; dd++) {
                float4 a0 = *(const float4*)(Ac + dd * 128 + ty * 4);
                float4 a1 = *(const float4*)(Ac + dd * 128 + ty * 4 + 64);
                float4 b0 = *(const float4*)(Bc + dd * BSTR + tx * 4);
                float4 b1 = *(const float4*)(Bc + dd * BSTR + tx * 4 + 64);
                float av[2][4] = {{a0.x, a0.y, a0.z, a0.w}, {a1.x, a1.y, a1.z, a1.w}};
                float bv[2][4] = {{b0.x, b0.y, b0.z, b0.w}, {b1.x, b1.y, b1.z, b1.w}};
#pragma unroll
                for (int h = 0; h < 2; h++)
#pragma unroll
                    for (int i = 0; i < 4; i++)
#pragma unroll
                        for (int g = 0; g < 2; g++)
#pragma unroll
                            for (int j = 0; j < 4; j++)
                                acc[h][i][g][j] = fmaf(av[h][i], bv[g][j], acc[h][i][g][j]);
            }
            if (ch < 15) {
#pragma unroll
                for (int j = 0; j < 8; j++) {
                    int l = j * 256 + t; int d = l & 15; int k = l >> 4;
                    Bs[(cur ^ 1) * BBUF + d * BSTR + k] = rb[j];
                }
            }
            __syncthreads();
        }

        // fold tile into running argmin (c ascending per thread -> first-min rule via strict <)
#pragma unroll
        for (int g = 0; g < 2; g++)
#pragma unroll
            for (int j = 0; j < 4; j++) {
                int c = k0 + g * 64 + tx * 4 + j;
                float cn = g_cnorm[c];
#pragma unroll
                for (int h = 0; h < 2; h++)
#pragma unroll
                    for (int i = 0; i < 4; i++) {
                        float v = fmaf(-2.f, acc[h][i][g][j], cn);
                        if (v < best[h][i]) { best[h][i] = v; bidx[h][i] = c; }
                    }
            }
    }

    // ---- argmin reduce across tx (16 threads share each row group) ----
#pragma unroll
    for (int off = 8; off; off >>= 1) {
#pragma unroll
        for (int h = 0; h < 2; h++)
#pragma unroll
            for (int i = 0; i < 4; i++) {
                float ov = __shfl_xor_sync(0xffffffffu, best[h][i], off, 16);
                int   oi = __shfl_xor_sync(0xffffffffu, bidx[h][i], off, 16);
                if (ov < best[h][i] || (ov == best[h][i] && oi < bidx[h][i])) {
                    best[h][i] = ov; bidx[h][i] = oi;
                }
            }
    }
    if (tx == 0) {
#pragma unroll
        for (int h = 0; h < 2; h++)
#pragma unroll
            for (int i = 0; i < 4; i++)
                rowIdx[h * 64 + ty * 4 + i] = bidx[h][i];
    }
    __syncthreads();

    // ---- outputs: indices (as float), z_q_st, loss partial ----
    if (t < 128) out[IDX_OFF + n0 + t] = (float)rowIdx[t];

    float lsum = 0.f;
    float* outz = out + b * (D * HW) + hw0;
#pragma unroll 4
    for (int j = 0; j < 128; j++) {
        int l = j * 256 + t;
        int i = l & 127;
        int d = l >> 7;
        float ze = As[d * 128 + i];
        float zq = __ldg(cb + rowIdx[i] * D + d);
        float diff = zq - ze;                 // matches ref's (z_q - z_e)
        outz[d * HW + i] = ze + diff;         // matches ref's z_e + stop_grad(z_q - z_e)
        lsum = fmaf(diff, diff, lsum);
    }

    // deterministic block reduction of loss
#pragma unroll
    for (int off = 16; off; off >>= 1) lsum += __shfl_xor_sync(0xffffffffu, lsum, off);
    __shared__ float wsum[8];
    if ((t & 31) == 0) wsum[t >> 5] = lsum;
    __syncthreads();
    if (t == 0) {
        float s = 0.f;
#pragma unroll
        for (int w = 0; w < 8; w++) s += wsum[w];
        g_partial[blockIdx.x] = s;
    }
}

// ---------------------------------------------------------------------------
// Kernel 3: deterministic final loss reduction
// ---------------------------------------------------------------------------
__global__ void finalize_kernel(float* __restrict__ out) {
    float s = 0.f;
    for (int i = 0; i < NBLK; i++) s += g_partial[i];
    float mean = s / 8388608.f;
    out[LOSS_OFF] = mean + 0.25f * mean;   // codebook_loss + 0.25 * commitment_loss
}

// ---------------------------------------------------------------------------
extern "C" void kernel_launch(void* const* d_in, const int* in_sizes, int n_in,
                              void* d_out, int out_size) {
    const float* z  = (const float*)d_in[0];   // z_e  (32,256,32,32) f32
    const float* cb = (const float*)d_in[1];   // codebook (1024,256) f32
    float* out = (float*)d_out;

    cudaFuncSetAttribute(vq_main, cudaFuncAttributeMaxDynamicSharedMemorySize, SMEM_BYTES);

    cnorm_kernel<<<128, 256>>>(cb);
    vq_main<<<NBLK, 256, SMEM_BYTES>>>(z, cb, out);
    finalize_kernel<<<1, 1>>>(out);
}

// round 2
// speedup vs baseline: 1.0040x; 1.0040x over previous
#include <cuda_runtime.h>

// Problem constants
#define D      256
#define K      1024
#define HW     1024            // 32*32 spatial per batch
#define NTOK   32768           // 32 * 1024
#define NBLK   256             // main grid (NTOK / 128)
#define ZQN    8388608         // 32*256*32*32
#define IDX_OFF 8388608
#define LOSS_OFF 8421376

// B-tile smem geometry
#define BK    16
#define BSTR  132              // padded stride (words) to kill store conflicts
#define BBUF  (BK * BSTR)

#define SMEM_BYTES ((D * 128 + 2 * BBUF) * 4 + 128 * 4)   // A panel + B dbuf + rowIdx

__device__ float g_cnorm[K];
__device__ float g_partial[NBLK];

// ---------------------------------------------------------------------------
// Kernel 1: codebook squared norms
// ---------------------------------------------------------------------------
__global__ void cnorm_kernel(const float* __restrict__ cb) {
    int k    = blockIdx.x * 8 + (threadIdx.x >> 5);
    int lane = threadIdx.x & 31;
    const float* row = cb + k * D;
    float s = 0.f;
#pragma unroll
    for (int d = lane; d < D; d += 32) { float v = row[d]; s = fmaf(v, v, s); }
#pragma unroll
    for (int off = 16; off; off >>= 1) s += __shfl_xor_sync(0xffffffffu, s, off);
    if (lane == 0) g_cnorm[k] = s;
}

// ---------------------------------------------------------------------------
// Kernel 2: fused GEMM + argmin + gather + loss partials
// Block = 128 tokens x all 1024 codes. 256 threads, 8x8 micro-tiles.
// ---------------------------------------------------------------------------
__global__ __launch_bounds__(256, 1) void vq_main(const float* __restrict__ z,
                                                  const float* __restrict__ cb,
                                                  float* __restrict__ out) {
    extern __shared__ float sm[];
    float* As     = sm;                        // [256][128]  token panel (d-major)
    float* Bs     = sm + D * 128;              // [2][BK][BSTR]
    int*   rowIdx = (int*)(Bs + 2 * BBUF);     // [128]

    const int t   = threadIdx.x;
    const int tx  = t & 15;
    const int ty  = t >> 4;
    const int n0  = blockIdx.x * 128;
    const int b   = n0 >> 10;                  // batch index (128 | 1024 so no straddle)
    const int hw0 = n0 & 1023;
    const float* zb = z + b * (D * HW) + hw0;

    // ---- Load A panel: 128 tokens x 256 dims, stored As[d][token] ----
    {
        const int i4    = (t & 31) * 4;
        const int dbase = t >> 5;
#pragma unroll
        for (int j = 0; j < 32; j++) {
            int d = dbase + j * 8;
            float4 v = *(const float4*)(zb + d * HW + i4);
            *(float4*)(As + d * 128 + i4) = v;
        }
    }

    float best[2][4];
    int   bidx[2][4];
#pragma unroll
    for (int h = 0; h < 2; h++)
#pragma unroll
        for (int i = 0; i < 4; i++) { best[h][i] = 3.4e38f; bidx[h][i] = 0; }

    __syncthreads();

    // ---- Loop over 8 code tiles of 128 ----
    for (int tile = 0; tile < 8; tile++) {
        const int k0 = tile * 128;
        float acc[2][4][2][4];
#pragma unroll
        for (int h = 0; h < 2; h++)
#pragma unroll
            for (int i = 0; i < 4; i++)
#pragma unroll
                for (int g = 0; g < 2; g++)
#pragma unroll
                    for (int j = 0; j < 4; j++) acc[h][i][g][j] = 0.f;

        float rb[8];
        // prologue: chunk 0 -> Bs[0]
#pragma unroll
        for (int j = 0; j < 8; j++) {
            int l = j * 256 + t; int d = l & 15; int k = l >> 4;
            rb[j] = cb[(k0 + k) * D + d];
        }
#pragma unroll
        for (int j = 0; j < 8; j++) {
            int l = j * 256 + t; int d = l & 15; int k = l >> 4;
            Bs[d * BSTR + k] = rb[j];
        }
        __syncthreads();

        for (int ch = 0; ch < 16; ch++) {
            const int cur = ch & 1;
            if (ch < 15) {   // prefetch next chunk into registers
                const int dbase = (ch + 1) * BK;
#pragma unroll
                for (int j = 0; j < 8; j++) {
                    int l = j * 256 + t; int d = l & 15; int k = l >> 4;
                    rb[j] = cb[(k0 + k) * D + dbase + d];
                }
            }
            const float* Bc = Bs + cur * BBUF;
            const float* Ac = As + ch * BK * 128;
#pragma unroll
            for (int dd = 0; dd < BK; dd++) {
                float4 a0 = *(const float4*)(Ac + dd * 128 + ty * 4);
                float4 a1 = *(const float4*)(Ac + dd * 128 + ty * 4 + 64);
                float4 b0 = *(const float4*)(Bc + dd * BSTR + tx * 4);
                float4 b1 = *(const float4*)(Bc + dd * BSTR + tx * 4 + 64);
                float av[2][4] = {{a0.x, a0.y, a0.z, a0.w}, {a1.x, a1.y, a1.z, a1.w}};
                float bv[2][4] = {{b0.x, b0.y, b0.z, b0.w}, {b1.x, b1.y, b1.z, b1.w}};
#pragma unroll
                for (int h = 0; h < 2; h++)
#pragma unroll
                    for (int i = 0; i < 4; i++)
#pragma unroll
                        for (int g = 0; g < 2; g++)
#pragma unroll
                            for (int j = 0; j < 4; j++)
                                acc[h][i][g][j] = fmaf(av[h][i], bv[g][j], acc[h][i][g][j]);
            }
            if (ch < 15) {
#pragma unroll
                for (int j = 0; j < 8; j++) {
                    int l = j * 256 + t; int d = l & 15; int k = l >> 4;
                    Bs[(cur ^ 1) * BBUF + d * BSTR + k] = rb[j];
                }
            }
            __syncthreads();
        }

        // fold tile into running argmin (c ascending per thread -> first-min rule via strict <)
#pragma unroll
        for (int g = 0; g < 2; g++)
#pragma unroll
            for (int j = 0; j < 4; j++) {
                int c = k0 + g * 64 + tx * 4 + j;
                float cn = g_cnorm[c];
#pragma unroll
                for (int h = 0; h < 2; h++)
#pragma unroll
                    for (int i = 0; i < 4; i++) {
                        float v = fmaf(-2.f, acc[h][i][g][j], cn);
                        if (v < best[h][i]) { best[h][i] = v; bidx[h][i] = c; }
                    }
            }
    }

    // ---- argmin reduce across tx (16 threads share each row group) ----
#pragma unroll
    for (int off = 8; off; off >>= 1) {
#pragma unroll
        for (int h = 0; h < 2; h++)
#pragma unroll
            for (int i = 0; i < 4; i++) {
                float ov = __shfl_xor_sync(0xffffffffu, best[h][i], off, 16);
                int   oi = __shfl_xor_sync(0xffffffffu, bidx[h][i], off, 16);
                if (ov < best[h][i] || (ov == best[h][i] && oi < bidx[h][i])) {
                    best[h][i] = ov; bidx[h][i] = oi;
                }
            }
    }
    if (tx == 0) {
#pragma unroll
        for (int h = 0; h < 2; h++)
#pragma unroll
            for (int i = 0; i < 4; i++)
                rowIdx[h * 64 + ty * 4 + i] = bidx[h][i];
    }
    __syncthreads();

    // ---- outputs: indices (as float), z_q_st, loss partial ----
    if (t < 128) out[IDX_OFF + n0 + t] = (float)rowIdx[t];

    float lsum = 0.f;
    float* outz = out + b * (D * HW) + hw0;
#pragma unroll 4
    for (int j = 0; j < 128; j++) {
        int l = j * 256 + t;
        int i = l & 127;
        int d = l >> 7;
        float ze = As[d * 128 + i];
        float zq = __ldg(cb + rowIdx[i] * D + d);
        float diff = zq - ze;                 // matches ref's (z_q - z_e)
        outz[d * HW + i] = ze + diff;         // matches ref's z_e + stop_grad(z_q - z_e)
        lsum = fmaf(diff, diff, lsum);
    }

    // deterministic block reduction of loss
#pragma unroll
    for (int off = 16; off; off >>= 1) lsum += __shfl_xor_sync(0xffffffffu, lsum, off);
    __shared__ float wsum[8];
    if ((t & 31) == 0) wsum[t >> 5] = lsum;
    __syncthreads();
    if (t == 0) {
        float s = 0.f;
#pragma unroll
        for (int w = 0; w < 8; w++) s += wsum[w];
        g_partial[blockIdx.x] = s;
    }
}

// ---------------------------------------------------------------------------
// Kernel 3: deterministic final loss reduction
// ---------------------------------------------------------------------------
__global__ void finalize_kernel(float* __restrict__ out) {
    float s = 0.f;
    for (int i = 0; i < NBLK; i++) s += g_partial[i];
    float mean = s / 8388608.f;
    out[LOSS_OFF] = mean + 0.25f * mean;   // codebook_loss + 0.25 * commitment_loss
}

// ---------------------------------------------------------------------------
extern "C" void kernel_launch(void* const* d_in, const int* in_sizes, int n_in,
                              void* d_out, int out_size) {
    const float* z  = (const float*)d_in[0];   // z_e  (32,256,32,32) f32
    const float* cb = (const float*)d_in[1];   // codebook (1024,256) f32
    float* out = (float*)d_out;

    cudaFuncSetAttribute(vq_main, cudaFuncAttributeMaxDynamicSharedMemorySize, SMEM_BYTES);

    cnorm_kernel<<<128, 256>>>(cb);
    vq_main<<<NBLK, 256, SMEM_BYTES>>>(z, cb, out);
    finalize_kernel<<<1, 1>>>(out);
}

// round 4
// speedup vs baseline: 1.5546x; 1.5484x over previous
#include <cuda_runtime.h>
#include <cuda_bf16.h>
#include <cstdint>

#define D        256
#define K        1024
#define HW       1024
#define NTOK     32768
#define NBLK     256
#define IDX_OFF  8388608
#define LOSS_OFF 8421376
#define MARGIN   0.05f

// smem layout (bytes)
#define OFF_AH   0         // 128 tokens x 264 halves
#define OFF_AL   67584
#define OFF_B    135168    // 2 bufs x (2 halves x 32 codes x 264 halves)
#define BBUF_SZ  33792
#define BHALF_SZ 16896
#define OFF_CN   202752
#define OFF_STG  206848
#define SMEM_SZ  210944

__device__ float    g_cnorm[K];
__device__ float    g_partial[NBLK];
__device__ int      g_idx[NTOK];
__device__ int4     g_doubt[NTOK];
__device__ int      g_doubt_cnt;
__device__ uint16_t g_cbh[K * D];
__device__ uint16_t g_cbl[K * D];

// ---------------- helpers ----------------
__device__ __forceinline__ uint32_t smem_u32(const void* p) {
    uint32_t a;
    asm("{ .reg .u64 t; cvta.to.shared.u64 t, %1; cvt.u32.u64 %0, t; }" : "=r"(a) : "l"(p));
    return a;
}
#define CP_ASYNC16(dst, src) \
    asm volatile("cp.async.cg.shared.global [%0], [%1], 16;" :: "r"(dst), "l"(src) : "memory")
#define CP_COMMIT() asm volatile("cp.async.commit_group;" ::: "memory")
#define CP_WAIT1()  asm volatile("cp.async.wait_group 1;" ::: "memory")

__device__ __forceinline__ void mma_bf16(float* c, const uint32_t* a, const uint32_t* b) {
    asm volatile(
        "mma.sync.aligned.m16n8k16.row.col.f32.bf16.bf16.f32 "
        "{%0,%1,%2,%3}, {%4,%5,%6,%7}, {%8,%9}, {%0,%1,%2,%3};"
        : "+f"(c[0]), "+f"(c[1]), "+f"(c[2]), "+f"(c[3])
        : "r"(a[0]), "r"(a[1]), "r"(a[2]), "r"(a[3]), "r"(b[0]), "r"(b[1]));
}
__device__ __forceinline__ bool better(float v, int i, float V, int I) {
    return v < V || (v == V && i < I);
}

// ---------------- Kernel 0: split codebook to bf16 hi/lo ----------------
__global__ void prep_kernel(const float* __restrict__ cb) {
    int i = blockIdx.x * 256 + threadIdx.x;
    float v = cb[i];
    __nv_bfloat16 h = __float2bfloat16(v);
    g_cbh[i] = __bfloat16_as_ushort(h);
    g_cbl[i] = __bfloat16_as_ushort(__float2bfloat16(v - __bfloat162float(h)));
}

// ---------------- Kernel 1: cnorm + counter reset ----------------
__global__ void cnorm_kernel(const float* __restrict__ cb) {
    if (blockIdx.x == 0 && threadIdx.x == 0) g_doubt_cnt = 0;
    int k = blockIdx.x * 8 + (threadIdx.x >> 5);
    int lane = threadIdx.x & 31;
    const float* row = cb + k * D;
    float s = 0.f;
#pragma unroll
    for (int d = lane; d < D; d += 32) { float v = row[d]; s = fmaf(v, v, s); }
#pragma unroll
    for (int o = 16; o; o >>= 1) s += __shfl_xor_sync(~0u, s, o);
    if (lane == 0) g_cnorm[k] = s;
}

// ---------------- Kernel 2: HMMA bf16x3 GEMM + top-2 argmin ----------------
__global__ __launch_bounds__(256, 1) void vq_gemm(const float* __restrict__ z) {
    extern __shared__ char sm[];
    const uint32_t su = smem_u32(sm);
    const int t = threadIdx.x, w = t >> 5, lane = t & 31;
    const int g = lane >> 2, p = lane & 3;
    const int mw = w >> 1, nw = w & 1;
    const int n0 = blockIdx.x * 128;
    const int b = n0 >> 10, hw0 = n0 & 1023;
    const float* zb = z + b * (D * HW) + hw0;

    uint16_t* sAh = (uint16_t*)(sm + OFF_AH);
    uint16_t* sAl = (uint16_t*)(sm + OFF_AL);
    float*    scn = (float*)(sm + OFF_CN);
    float4*   stg = (float4*)(sm + OFF_STG);

    // ---- A: load z coalesced, split hi/lo into padded smem [tok][dim] ----
#pragma unroll
    for (int j = 0; j < 32; j++) {
        int l = j * 256 + t;
        int d = l >> 5, f4 = l & 31;
        float4 v = *(const float4*)(zb + d * HW + f4 * 4);
        float vv[4] = {v.x, v.y, v.z, v.w};
#pragma unroll
        for (int q = 0; q < 4; q++) {
            int tok = f4 * 4 + q;
            __nv_bfloat16 h = __float2bfloat16(vv[q]);
            sAh[tok * 264 + d] = __bfloat16_as_ushort(h);
            sAl[tok * 264 + d] =
                __bfloat16_as_ushort(__float2bfloat16(vv[q] - __bfloat162float(h)));
        }
    }
    for (int c = t; c < K; c += 256) scn[c] = g_cnorm[c];

    // prefetch B chunk 0 (codes 0..31, hi+lo) via cp.async
    {
#pragma unroll
        for (int j = 0; j < 8; j++) {
            int s = j * 256 + t;
            int half = s >> 10, code = (s >> 5) & 31, seg = s & 31;
            uint32_t dst = su + OFF_B + half * BHALF_SZ + code * 528 + seg * 16;
            const char* srcb = (const char*)(half ? g_cbl : g_cbh) + code * 512 + seg * 16;
            CP_ASYNC16(dst, srcb);
        }
        CP_COMMIT();
    }
    __syncthreads();   // A panel + cnorm visible

    // per-thread top-2 for 4 tokens [mt][rr]
    float rv1[2][2], rv2[2][2];
    int   ri1[2][2], ri2[2][2];
#pragma unroll
    for (int mt = 0; mt < 2; mt++)
#pragma unroll
        for (int rr = 0; rr < 2; rr++) {
            rv1[mt][rr] = 3.4e38f; rv2[mt][rr] = 3.4e38f;
            ri1[mt][rr] = 0; ri2[mt][rr] = 0;
        }

    const uint32_t* Aw_h = (const uint32_t*)(sm + OFF_AH);
    const uint32_t* Aw_l = (const uint32_t*)(sm + OFF_AL);

    for (int nc = 0; nc < 32; nc++) {
        // issue next chunk
        if (nc < 31) {
            int nn = nc + 1, buf = nn & 1;
#pragma unroll
            for (int j = 0; j < 8; j++) {
                int s = j * 256 + t;
                int half = s >> 10, code = (s >> 5) & 31, seg = s & 31;
                uint32_t dst = su + OFF_B + buf * BBUF_SZ + half * BHALF_SZ + code * 528 + seg * 16;
                const char* srcb = (const char*)(half ? g_cbl : g_cbh)
                                 + (nn * 32 + code) * 512 + seg * 16;
                CP_ASYNC16(dst, srcb);
            }
        }
        CP_COMMIT();
        CP_WAIT1();
        __syncthreads();

        const uint32_t* Bw_h = (const uint32_t*)(sm + OFF_B + (nc & 1) * BBUF_SZ);
        const uint32_t* Bw_l = (const uint32_t*)(sm + OFF_B + (nc & 1) * BBUF_SZ + BHALF_SZ);

        float acc[2][2][4];
#pragma unroll
        for (int mt = 0; mt < 2; mt++)
#pragma unroll
            for (int nt = 0; nt < 2; nt++)
#pragma unroll
                for (int q = 0; q < 4; q++) acc[mt][nt][q] = 0.f;

#pragma unroll 4
        for (int ks = 0; ks < 16; ks++) {
            uint32_t ah[2][4], al[2][4];
#pragma unroll
            for (int mt = 0; mt < 2; mt++) {
                int row = mw * 32 + mt * 16 + g;
                int base = row * 132 + ks * 8 + p;
                ah[mt][0] = Aw_h[base];           ah[mt][1] = Aw_h[base + 8 * 132];
                ah[mt][2] = Aw_h[base + 4];       ah[mt][3] = Aw_h[base + 8 * 132 + 4];
                al[mt][0] = Aw_l[base];           al[mt][1] = Aw_l[base + 8 * 132];
                al[mt][2] = Aw_l[base + 4];       al[mt][3] = Aw_l[base + 8 * 132 + 4];
            }
            uint32_t bh[2][2], bl[2][2];
#pragma unroll
            for (int nt = 0; nt < 2; nt++) {
                int code = nw * 16 + nt * 8 + g;
                int base = code * 132 + ks * 8 + p;
                bh[nt][0] = Bw_h[base]; bh[nt][1] = Bw_h[base + 4];
                bl[nt][0] = Bw_l[base]; bl[nt][1] = Bw_l[base + 4];
            }
#pragma unroll
            for (int mt = 0; mt < 2; mt++)
#pragma unroll
                for (int nt = 0; nt < 2; nt++) {
                    mma_bf16(acc[mt][nt], ah[mt], bh[nt]);
                    mma_bf16(acc[mt][nt], ah[mt], bl[nt]);
                    mma_bf16(acc[mt][nt], al[mt], bh[nt]);
                }
        }

        // fold chunk into running top-2 (codes ascending per thread)
#pragma unroll
        for (int nt = 0; nt < 2; nt++)
#pragma unroll
            for (int q = 0; q < 2; q++) {
                int c = nc * 32 + nw * 16 + nt * 8 + 2 * p + q;
                float cn = scn[c];
#pragma unroll
                for (int mt = 0; mt < 2; mt++)
#pragma unroll
                    for (int rr = 0; rr < 2; rr++) {
                        float v = fmaf(-2.f, acc[mt][nt][rr * 2 + q], cn);
                        if (v < rv1[mt][rr]) {
                            rv2[mt][rr] = rv1[mt][rr]; ri2[mt][rr] = ri1[mt][rr];
                            rv1[mt][rr] = v;           ri1[mt][rr] = c;
                        } else if (v < rv2[mt][rr]) {
                            rv2[mt][rr] = v;           ri2[mt][rr] = c;
                        }
                    }
            }
        __syncthreads();
    }

    // ---- merge top-2 across p lanes (xor 1, 2) ----
#pragma unroll
    for (int o = 1; o <= 2; o <<= 1) {
#pragma unroll
        for (int mt = 0; mt < 2; mt++)
#pragma unroll
            for (int rr = 0; rr < 2; rr++) {
                float ov1 = __shfl_xor_sync(~0u, rv1[mt][rr], o);
                int   oi1 = __shfl_xor_sync(~0u, ri1[mt][rr], o);
                float ov2 = __shfl_xor_sync(~0u, rv2[mt][rr], o);
                int   oi2 = __shfl_xor_sync(~0u, ri2[mt][rr], o);
                if (better(ov1, oi1, rv1[mt][rr], ri1[mt][rr])) {
                    if (better(rv1[mt][rr], ri1[mt][rr], ov2, oi2)) {
                        rv2[mt][rr] = rv1[mt][rr]; ri2[mt][rr] = ri1[mt][rr];
                    } else { rv2[mt][rr] = ov2; ri2[mt][rr] = oi2; }
                    rv1[mt][rr] = ov1; ri1[mt][rr] = oi1;
                } else if (better(ov1, oi1, rv2[mt][rr], ri2[mt][rr])) {
                    rv2[mt][rr] = ov1; ri2[mt][rr] = oi1;
                }
            }
    }
    if (p == 0) {
#pragma unroll
        for (int mt = 0; mt < 2; mt++)
#pragma unroll
            for (int rr = 0; rr < 2; rr++) {
                int tok = mw * 32 + mt * 16 + rr * 8 + g;
                stg[tok * 2 + nw] = make_float4(rv1[mt][rr], __int_as_float(ri1[mt][rr]),
                                                rv2[mt][rr], __int_as_float(ri2[mt][rr]));
            }
    }
    __syncthreads();

    if (t < 128) {
        float4 a = stg[t * 2], bq = stg[t * 2 + 1];
        float v1 = a.x, v2 = a.z; int i1 = __float_as_int(a.y), i2 = __float_as_int(a.w);
        float w1 = bq.x, w2 = bq.z; int j1 = __float_as_int(bq.y), j2 = __float_as_int(bq.w);
        float fv1, fv2; int fi1, fi2;
        if (better(w1, j1, v1, i1)) {
            fv1 = w1; fi1 = j1;
            if (better(v1, i1, w2, j2)) { fv2 = v1; fi2 = i1; } else { fv2 = w2; fi2 = j2; }
        } else {
            fv1 = v1; fi1 = i1;
            if (better(w1, j1, v2, i2)) { fv2 = w1; fi2 = j1; } else { fv2 = v2; fi2 = i2; }
        }
        g_idx[n0 + t] = fi1;
        if (fv2 - fv1 < MARGIN) {
            int s = atomicAdd(&g_doubt_cnt, 1);
            g_doubt[s] = make_int4(n0 + t, fi1, fi2, 0);
        }
    }
}

// ---------------- Kernel 3: exact fp32 rescue ----------------
__global__ void rescue_kernel(const float* __restrict__ z, const float* __restrict__ cb) {
    int wid = (blockIdx.x * blockDim.x + threadIdx.x) >> 5;
    int lane = threadIdx.x & 31;
    int stride = (gridDim.x * blockDim.x) >> 5;
    int cnt = g_doubt_cnt;
    for (int i = wid; i < cnt; i += stride) {
        int4 dq = g_doubt[i];
        int n = dq.x, c1 = dq.y, c2 = dq.z;
        int bb = n >> 10, hw = n & 1023;
        const float* zp = z + bb * (D * HW) + hw;
        const float* p1 = cb + c1 * D;
        const float* p2 = cb + c2 * D;
        float zz = 0.f, d1 = 0.f, d2 = 0.f;
#pragma unroll
        for (int d = lane; d < D; d += 32) {
            float ze = zp[d * HW];
            zz = fmaf(ze, ze, zz);
            d1 = fmaf(ze, p1[d], d1);
            d2 = fmaf(ze, p2[d], d2);
        }
#pragma unroll
        for (int o = 16; o; o >>= 1) {
            zz += __shfl_xor_sync(~0u, zz, o);
            d1 += __shfl_xor_sync(~0u, d1, o);
            d2 += __shfl_xor_sync(~0u, d2, o);
        }
        if (lane == 0) {
            float D1 = __fadd_rn(__fsub_rn(zz, __fmul_rn(2.f, d1)), g_cnorm[c1]);
            float D2 = __fadd_rn(__fsub_rn(zz, __fmul_rn(2.f, d2)), g_cnorm[c2]);
            int win = (D2 < D1 || (D2 == D1 && c2 < c1)) ? c2 : c1;
            g_idx[n] = win;
        }
    }
}

// ---------------- Kernel 4: outputs ----------------
__global__ __launch_bounds__(256) void vq_out(const float* __restrict__ z,
                                              const float* __restrict__ cb,
                                              float* __restrict__ out) {
    __shared__ int rowIdx[128];
    __shared__ float wsum[8];
    const int t = threadIdx.x;
    const int n0 = blockIdx.x * 128;
    const int b = n0 >> 10, hw0 = n0 & 1023;
    if (t < 128) {
        int idx = g_idx[n0 + t];
        rowIdx[t] = idx;
        out[IDX_OFF + n0 + t] = (float)idx;
    }
    __syncthreads();
    const float* zb = z + b * (D * HW) + hw0;
    float* outz = out + b * (D * HW) + hw0;
    float lsum = 0.f;
#pragma unroll 4
    for (int j = 0; j < 128; j++) {
        int l = j * 256 + t;
        int i = l & 127, d = l >> 7;
        float ze = zb[d * HW + i];
        float zq = __ldg(cb + rowIdx[i] * D + d);
        float diff = zq - ze;
        outz[d * HW + i] = ze + diff;
        lsum = fmaf(diff, diff, lsum);
    }
#pragma unroll
    for (int o = 16; o; o >>= 1) lsum += __shfl_xor_sync(~0u, lsum, o);
    if ((t & 31) == 0) wsum[t >> 5] = lsum;
    __syncthreads();
    if (t == 0) {
        float s = 0.f;
#pragma unroll
        for (int ww = 0; ww < 8; ww++) s += wsum[ww];
        g_partial[blockIdx.x] = s;
    }
}

__global__ void finalize_kernel(float* __restrict__ out) {
    float s = 0.f;
    for (int i = 0; i < NBLK; i++) s += g_partial[i];
    float mean = s / 8388608.f;
    out[LOSS_OFF] = mean + 0.25f * mean;
}

// ---------------------------------------------------------------------------
extern "C" void kernel_launch(void* const* d_in, const int* in_sizes, int n_in,
                              void* d_out, int out_size) {
    const float* z  = (const float*)d_in[0];
    const float* cb = (const float*)d_in[1];
    float* out = (float*)d_out;

    cudaFuncSetAttribute(vq_gemm, cudaFuncAttributeMaxDynamicSharedMemorySize, SMEM_SZ);

    prep_kernel<<<1024, 256>>>(cb);
    cnorm_kernel<<<128, 256>>>(cb);
    vq_gemm<<<NBLK, 256, SMEM_SZ>>>(z);
    rescue_kernel<<<32, 256>>>(z, cb);
    vq_out<<<NBLK, 256>>>(z, cb, out);
    finalize_kernel<<<1, 1>>>(out);
}